// round 7
// baseline (speedup 1.0000x reference)
#include <cuda_runtime.h>
#include <math.h>
#include <stdint.h>

// Problem constants (from reference)
#define L_A        128
#define B_DIM      64
#define NUM_PAIRS  (L_A * B_DIM)   // 8192
#define NUM_RULES  256
#define NUM_TOKENS 32000
#define MAX_QUERY  512
#define EPS_VAL    1e-7f

#define MAX_CTAS   16

__device__ float g_partials[128];   // used only by the PDL fallback path

__device__ __forceinline__ float gather_or_zero(const float* __restrict__ p,
                                                int pair, int stride, int idx) {
    // idx == -1 contributes 0 (matches reference _gather_prob)
    int safe = idx < 0 ? 0 : idx;
    float v = __ldg(p + (long long)pair * stride + safe);
    return (idx == -1) ? 0.0f : v;
}

__device__ __forceinline__ float compute_loss(const float* __restrict__ rule_prob,
                                              const float* __restrict__ token_prob,
                                              const float* __restrict__ copy_prob,
                                              const int*   __restrict__ gt_rule,
                                              const int*   __restrict__ gt_token,
                                              const int*   __restrict__ gt_copy,
                                              const float* __restrict__ mask,
                                              int pair) {
    int r = gt_rule[pair];
    int t = gt_token[pair];
    int c = gt_copy[pair];
    float m = mask[pair];

    float prob = gather_or_zero(rule_prob,  pair, NUM_RULES,  r)
               + gather_or_zero(token_prob, pair, NUM_TOKENS, t)
               + gather_or_zero(copy_prob,  pair, MAX_QUERY,  c);

    // reference: prob = prob + (prob < EPS) * EPS   (an add, not a clamp)
    if (prob < EPS_VAL) prob += EPS_VAL;
    return -logf(prob) * m;
}

__device__ __forceinline__ float warp_reduce(float v) {
    #pragma unroll
    for (int off = 16; off > 0; off >>= 1)
        v += __shfl_xor_sync(0xFFFFFFFFu, v, off);
    return v;
}

// ─────────────────────────────── single-node cluster kernel ──────────────────
__global__ void __launch_bounds__(1024, 1)
loss_cluster_kernel(const float* __restrict__ rule_prob,
                    const float* __restrict__ token_prob,
                    const float* __restrict__ copy_prob,
                    const int*   __restrict__ gt_rule,
                    const int*   __restrict__ gt_token,
                    const int*   __restrict__ gt_copy,
                    const float* __restrict__ mask,
                    float*       __restrict__ out) {
    __shared__ float warp_sums[32];
    __shared__ float slots[MAX_CTAS];   // CTA 0's copy receives everyone's partial

    int pair = blockIdx.x * blockDim.x + threadIdx.x;   // grid covers 8192 exactly
    float loss = compute_loss(rule_prob, token_prob, copy_prob,
                              gt_rule, gt_token, gt_copy, mask, pair);

    // block reduce
    loss = warp_reduce(loss);
    int lane = threadIdx.x & 31;
    int wid  = threadIdx.x >> 5;
    int nwarps = blockDim.x >> 5;
    if (lane == 0) warp_sums[wid] = loss;
    __syncthreads();

    if (wid == 0) {
        float v = (lane < nwarps) ? warp_sums[lane] : 0.0f;
        v = warp_reduce(v);
        if (lane == 0) {
            // store this CTA's partial into CTA 0's slots[rank] via DSMEM
            uint32_t rank;
            asm("mov.u32 %0, %%cluster_ctarank;" : "=r"(rank));
            uint32_t local = (uint32_t)__cvta_generic_to_shared(&slots[rank]);
            uint32_t remote;
            asm("mapa.shared::cluster.u32 %0, %1, %2;"
                : "=r"(remote) : "r"(local), "r"(0));
            asm volatile("st.shared::cluster.f32 [%0], %1;"
                         :: "r"(remote), "f"(v) : "memory");
        }
    }

    // cluster barrier: arrive has release, wait has acquire -> DSMEM stores visible
    asm volatile("barrier.cluster.arrive.aligned;" ::: "memory");
    asm volatile("barrier.cluster.wait.aligned;"   ::: "memory");

    uint32_t rank;
    asm("mov.u32 %0, %%cluster_ctarank;" : "=r"(rank));
    if (rank == 0 && wid == 0) {
        int ncta = gridDim.x;     // grid == one cluster
        float x = (lane < ncta) ? slots[lane] : 0.0f;
        x = warp_reduce(x);
        if (lane == 0) out[0] = x * (1.0f / (float)B_DIM);
    }
}

// ─────────────────────────────── PDL 2-kernel fallback ───────────────────────
#define FB_BLOCKS  128
#define FB_THREADS 64

__global__ void __launch_bounds__(FB_THREADS, 1)
loss_gather_kernel(const float* __restrict__ rule_prob,
                   const float* __restrict__ token_prob,
                   const float* __restrict__ copy_prob,
                   const int*   __restrict__ gt_rule,
                   const int*   __restrict__ gt_token,
                   const int*   __restrict__ gt_copy,
                   const float* __restrict__ mask) {
    asm volatile("griddepcontrol.launch_dependents;" ::: "memory");

    int pair = blockIdx.x * blockDim.x + threadIdx.x;
    float loss = compute_loss(rule_prob, token_prob, copy_prob,
                              gt_rule, gt_token, gt_copy, mask, pair);

    loss = warp_reduce(loss);
    __shared__ float warp_sums[FB_THREADS / 32];
    int lane = threadIdx.x & 31;
    int wid  = threadIdx.x >> 5;
    if (lane == 0) warp_sums[wid] = loss;
    __syncthreads();
    if (threadIdx.x == 0)
        g_partials[blockIdx.x] = warp_sums[0] + warp_sums[1];
}

__global__ void loss_final_kernel(float* __restrict__ out) {
    asm volatile("griddepcontrol.wait;" ::: "memory");
    int lane = threadIdx.x;
    float4 p = *((const float4*)g_partials + lane);
    float v = (p.x + p.y) + (p.z + p.w);
    v = warp_reduce(v);
    if (lane == 0) out[0] = v * (1.0f / (float)B_DIM);
}

// ─────────────────────────────── launch ──────────────────────────────────────
extern "C" void kernel_launch(void* const* d_in, const int* in_sizes, int n_in,
                              void* d_out, int out_size) {
    const float* rule_prob  = (const float*)d_in[0];
    const float* token_prob = (const float*)d_in[1];
    const float* copy_prob  = (const float*)d_in[2];
    const int*   gt_rule    = (const int*)  d_in[3];
    const int*   gt_token   = (const int*)  d_in[4];
    const int*   gt_copy    = (const int*)  d_in[5];
    const float* mask       = (const float*)d_in[6];
    float* out = (float*)d_out;

    // Attempt 1: one cluster of 16 CTAs x 512 threads (nonportable size)
    cudaFuncSetAttribute(loss_cluster_kernel,
                         cudaFuncAttributeNonPortableClusterSizeAllowed, 1);

    cudaLaunchAttribute cattrs[1];
    cattrs[0].id = cudaLaunchAttributeClusterDimension;
    cattrs[0].val.clusterDim = {16, 1, 1};

    cudaLaunchConfig_t ccfg = {};
    ccfg.gridDim  = dim3(16, 1, 1);
    ccfg.blockDim = dim3(512, 1, 1);
    ccfg.dynamicSmemBytes = 0;
    ccfg.stream = 0;
    ccfg.attrs = cattrs;
    ccfg.numAttrs = 1;

    cudaError_t err = cudaLaunchKernelEx(&ccfg, loss_cluster_kernel,
                                         rule_prob, token_prob, copy_prob,
                                         gt_rule, gt_token, gt_copy, mask, out);
    if (err == cudaSuccess) return;
    cudaGetLastError();   // clear sticky error

    // Attempt 2: portable cluster of 8 CTAs x 1024 threads
    cattrs[0].val.clusterDim = {8, 1, 1};
    ccfg.gridDim  = dim3(8, 1, 1);
    ccfg.blockDim = dim3(1024, 1, 1);
    err = cudaLaunchKernelEx(&ccfg, loss_cluster_kernel,
                             rule_prob, token_prob, copy_prob,
                             gt_rule, gt_token, gt_copy, mask, out);
    if (err == cudaSuccess) return;
    cudaGetLastError();

    // Attempt 3: proven 2-kernel PDL path
    loss_gather_kernel<<<FB_BLOCKS, FB_THREADS>>>(rule_prob, token_prob, copy_prob,
                                                  gt_rule, gt_token, gt_copy, mask);
    cudaLaunchAttribute attrs[1];
    attrs[0].id = cudaLaunchAttributeProgrammaticStreamSerialization;
    attrs[0].val.programmaticStreamSerializationAllowed = 1;

    cudaLaunchConfig_t cfg = {};
    cfg.gridDim  = dim3(1, 1, 1);
    cfg.blockDim = dim3(32, 1, 1);
    cfg.dynamicSmemBytes = 0;
    cfg.stream = 0;
    cfg.attrs = attrs;
    cfg.numAttrs = 1;
    if (cudaLaunchKernelEx(&cfg, loss_final_kernel, out) != cudaSuccess) {
        cudaGetLastError();
        loss_final_kernel<<<1, 32>>>(out);
    }
}

// round 8
// speedup vs baseline: 1.0385x; 1.0385x over previous
#include <cuda_runtime.h>
#include <math.h>
#include <stdint.h>

// Problem constants (from reference)
#define L_A        128
#define B_DIM      64
#define NUM_PAIRS  (L_A * B_DIM)   // 8192
#define NUM_RULES  256
#define NUM_TOKENS 32000
#define MAX_QUERY  512
#define EPS_VAL    1e-7f

#define MAX_CTAS   16

__device__ float g_partials[128];   // used only by the PDL fallback path

__device__ __forceinline__ float gather_or_zero(const float* __restrict__ p,
                                                int pair, int stride, int idx) {
    // idx == -1 contributes 0 (matches reference _gather_prob)
    int safe = idx < 0 ? 0 : idx;
    float v = __ldg(p + (long long)pair * stride + safe);
    return (idx == -1) ? 0.0f : v;
}

__device__ __forceinline__ float compute_loss(const float* __restrict__ rule_prob,
                                              const float* __restrict__ token_prob,
                                              const float* __restrict__ copy_prob,
                                              const int*   __restrict__ gt_rule,
                                              const int*   __restrict__ gt_token,
                                              const int*   __restrict__ gt_copy,
                                              const float* __restrict__ mask,
                                              int pair) {
    int r = gt_rule[pair];
    int t = gt_token[pair];
    int c = gt_copy[pair];
    float m = mask[pair];

    float prob = gather_or_zero(rule_prob,  pair, NUM_RULES,  r)
               + gather_or_zero(token_prob, pair, NUM_TOKENS, t)
               + gather_or_zero(copy_prob,  pair, MAX_QUERY,  c);

    // reference: prob = prob + (prob < EPS) * EPS   (an add, not a clamp)
    if (prob < EPS_VAL) prob += EPS_VAL;

    // __logf: MUFU.LG2 * ln2 — rel err ~2^-21, far inside the 1e-3 tolerance.
    // Inputs here are in (EPS, 3): well-conditioned for the fast path.
    return -__logf(prob) * m;
}

__device__ __forceinline__ float warp_reduce(float v) {
    #pragma unroll
    for (int off = 16; off > 0; off >>= 1)
        v += __shfl_xor_sync(0xFFFFFFFFu, v, off);
    return v;
}

// ─────────────────────────────── single-node cluster kernel ──────────────────
__global__ void __launch_bounds__(1024, 1)
loss_cluster_kernel(const float* __restrict__ rule_prob,
                    const float* __restrict__ token_prob,
                    const float* __restrict__ copy_prob,
                    const int*   __restrict__ gt_rule,
                    const int*   __restrict__ gt_token,
                    const int*   __restrict__ gt_copy,
                    const float* __restrict__ mask,
                    float*       __restrict__ out) {
    __shared__ float warp_sums[32];
    __shared__ float slots[MAX_CTAS];   // CTA 0's copy receives everyone's partial

    int pair = blockIdx.x * blockDim.x + threadIdx.x;   // grid covers 8192 exactly
    float loss = compute_loss(rule_prob, token_prob, copy_prob,
                              gt_rule, gt_token, gt_copy, mask, pair);

    // block reduce
    loss = warp_reduce(loss);
    int lane = threadIdx.x & 31;
    int wid  = threadIdx.x >> 5;
    int nwarps = blockDim.x >> 5;
    if (lane == 0) warp_sums[wid] = loss;
    __syncthreads();

    if (wid == 0) {
        float v = (lane < nwarps) ? warp_sums[lane] : 0.0f;
        v = warp_reduce(v);
        if (lane == 0) {
            // store this CTA's partial into CTA 0's slots[rank] via DSMEM
            uint32_t rank;
            asm("mov.u32 %0, %%cluster_ctarank;" : "=r"(rank));
            uint32_t local = (uint32_t)__cvta_generic_to_shared(&slots[rank]);
            uint32_t remote;
            asm("mapa.shared::cluster.u32 %0, %1, %2;"
                : "=r"(remote) : "r"(local), "r"(0));
            asm volatile("st.shared::cluster.f32 [%0], %1;"
                         :: "r"(remote), "f"(v) : "memory");
        }
    }

    // cluster barrier: arrive has release, wait has acquire -> DSMEM stores visible
    asm volatile("barrier.cluster.arrive.aligned;" ::: "memory");
    asm volatile("barrier.cluster.wait.aligned;"   ::: "memory");

    uint32_t rank;
    asm("mov.u32 %0, %%cluster_ctarank;" : "=r"(rank));
    if (rank == 0 && wid == 0) {
        int ncta = gridDim.x;     // grid == one cluster
        float x = (lane < ncta) ? slots[lane] : 0.0f;
        x = warp_reduce(x);
        if (lane == 0) out[0] = x * (1.0f / (float)B_DIM);
    }
}

// ─────────────────────────────── PDL 2-kernel fallback ───────────────────────
#define FB_BLOCKS  128
#define FB_THREADS 64

__global__ void __launch_bounds__(FB_THREADS, 1)
loss_gather_kernel(const float* __restrict__ rule_prob,
                   const float* __restrict__ token_prob,
                   const float* __restrict__ copy_prob,
                   const int*   __restrict__ gt_rule,
                   const int*   __restrict__ gt_token,
                   const int*   __restrict__ gt_copy,
                   const float* __restrict__ mask) {
    asm volatile("griddepcontrol.launch_dependents;" ::: "memory");

    int pair = blockIdx.x * blockDim.x + threadIdx.x;
    float loss = compute_loss(rule_prob, token_prob, copy_prob,
                              gt_rule, gt_token, gt_copy, mask, pair);

    loss = warp_reduce(loss);
    __shared__ float warp_sums[FB_THREADS / 32];
    int lane = threadIdx.x & 31;
    int wid  = threadIdx.x >> 5;
    if (lane == 0) warp_sums[wid] = loss;
    __syncthreads();
    if (threadIdx.x == 0)
        g_partials[blockIdx.x] = warp_sums[0] + warp_sums[1];
}

__global__ void loss_final_kernel(float* __restrict__ out) {
    asm volatile("griddepcontrol.wait;" ::: "memory");
    int lane = threadIdx.x;
    float4 p = *((const float4*)g_partials + lane);
    float v = (p.x + p.y) + (p.z + p.w);
    v = warp_reduce(v);
    if (lane == 0) out[0] = v * (1.0f / (float)B_DIM);
}

// ─────────────────────────────── launch ──────────────────────────────────────
extern "C" void kernel_launch(void* const* d_in, const int* in_sizes, int n_in,
                              void* d_out, int out_size) {
    const float* rule_prob  = (const float*)d_in[0];
    const float* token_prob = (const float*)d_in[1];
    const float* copy_prob  = (const float*)d_in[2];
    const int*   gt_rule    = (const int*)  d_in[3];
    const int*   gt_token   = (const int*)  d_in[4];
    const int*   gt_copy    = (const int*)  d_in[5];
    const float* mask       = (const float*)d_in[6];
    float* out = (float*)d_out;

    // Attempt 1: one cluster of 16 CTAs x 512 threads (nonportable size)
    cudaFuncSetAttribute(loss_cluster_kernel,
                         cudaFuncAttributeNonPortableClusterSizeAllowed, 1);

    cudaLaunchAttribute cattrs[1];
    cattrs[0].id = cudaLaunchAttributeClusterDimension;
    cattrs[0].val.clusterDim = {16, 1, 1};

    cudaLaunchConfig_t ccfg = {};
    ccfg.gridDim  = dim3(16, 1, 1);
    ccfg.blockDim = dim3(512, 1, 1);
    ccfg.dynamicSmemBytes = 0;
    ccfg.stream = 0;
    ccfg.attrs = cattrs;
    ccfg.numAttrs = 1;

    cudaError_t err = cudaLaunchKernelEx(&ccfg, loss_cluster_kernel,
                                         rule_prob, token_prob, copy_prob,
                                         gt_rule, gt_token, gt_copy, mask, out);
    if (err == cudaSuccess) return;
    cudaGetLastError();   // clear sticky error

    // Attempt 2: portable cluster of 8 CTAs x 1024 threads
    cattrs[0].val.clusterDim = {8, 1, 1};
    ccfg.gridDim  = dim3(8, 1, 1);
    ccfg.blockDim = dim3(1024, 1, 1);
    err = cudaLaunchKernelEx(&ccfg, loss_cluster_kernel,
                             rule_prob, token_prob, copy_prob,
                             gt_rule, gt_token, gt_copy, mask, out);
    if (err == cudaSuccess) return;
    cudaGetLastError();

    // Attempt 3: proven 2-kernel PDL path
    loss_gather_kernel<<<FB_BLOCKS, FB_THREADS>>>(rule_prob, token_prob, copy_prob,
                                                  gt_rule, gt_token, gt_copy, mask);
    cudaLaunchAttribute attrs[1];
    attrs[0].id = cudaLaunchAttributeProgrammaticStreamSerialization;
    attrs[0].val.programmaticStreamSerializationAllowed = 1;

    cudaLaunchConfig_t cfg = {};
    cfg.gridDim  = dim3(1, 1, 1);
    cfg.blockDim = dim3(32, 1, 1);
    cfg.dynamicSmemBytes = 0;
    cfg.stream = 0;
    cfg.attrs = attrs;
    cfg.numAttrs = 1;
    if (cudaLaunchKernelEx(&cfg, loss_final_kernel, out) != cudaSuccess) {
        cudaGetLastError();
        loss_final_kernel<<<1, 32>>>(out);
    }
}

// round 11
// speedup vs baseline: 1.0435x; 1.0048x over previous
#include <cuda_runtime.h>
#include <math.h>

// Problem constants (from reference)
#define L_A        128
#define B_DIM      64
#define NUM_PAIRS  (L_A * B_DIM)   // 8192
#define NUM_RULES  256
#define NUM_TOKENS 32000
#define MAX_QUERY  512
#define EPS_VAL    1e-7f

#define BLOCKS   64
#define THREADS  128   // BLOCKS * THREADS == NUM_PAIRS

__device__ float g_partials[BLOCKS];

__device__ __forceinline__ float gather_or_zero(const float* __restrict__ p,
                                                int pair, int stride, int idx) {
    // idx == -1 contributes 0 (matches reference _gather_prob)
    int safe = idx < 0 ? 0 : idx;
    float v = __ldg(p + (long long)pair * stride + safe);
    return (idx == -1) ? 0.0f : v;
}

__device__ __forceinline__ float warp_reduce(float v) {
    #pragma unroll
    for (int off = 16; off > 0; off >>= 1)
        v += __shfl_xor_sync(0xFFFFFFFFu, v, off);
    return v;
}

__global__ void __launch_bounds__(THREADS, 1)
loss_gather_kernel(const float* __restrict__ rule_prob,
                   const float* __restrict__ token_prob,
                   const float* __restrict__ copy_prob,
                   const int*   __restrict__ gt_rule,
                   const int*   __restrict__ gt_token,
                   const int*   __restrict__ gt_copy,
                   const float* __restrict__ mask) {
    // PDL: allow the dependent (final) kernel to begin its launch now; its
    // griddepcontrol.wait still gates on this grid's full memory flush.
    asm volatile("griddepcontrol.launch_dependents;" ::: "memory");

    int pair = blockIdx.x * blockDim.x + threadIdx.x;   // 0..8191

    // Indices first (independent), then all 3 gathers (independent -> MLP >= 3)
    int r = gt_rule[pair];
    int t = gt_token[pair];
    int c = gt_copy[pair];
    float m = mask[pair];

    float prob = gather_or_zero(rule_prob,  pair, NUM_RULES,  r)
               + gather_or_zero(token_prob, pair, NUM_TOKENS, t)
               + gather_or_zero(copy_prob,  pair, MAX_QUERY,  c);

    // reference: prob = prob + (prob < EPS) * EPS   (an add, not a clamp)
    if (prob < EPS_VAL) prob += EPS_VAL;

    // __logf: MUFU.LG2 * ln2 — rel err ~2^-21 vs 1e-3 tolerance.
    // prob is in (EPS, 3): well-conditioned for the fast path.
    float loss = -__logf(prob) * m;

    // --- block reduction: warp shuffle, then 4-warp combine via shared ---
    loss = warp_reduce(loss);

    __shared__ float warp_sums[THREADS / 32];   // 4
    int lane = threadIdx.x & 31;
    int wid  = threadIdx.x >> 5;
    if (lane == 0) warp_sums[wid] = loss;
    __syncthreads();

    if (threadIdx.x == 0)
        g_partials[blockIdx.x] = (warp_sums[0] + warp_sums[1])
                               + (warp_sums[2] + warp_sums[3]);
}

__global__ void loss_final_kernel(float* __restrict__ out) {
    // PDL: wait until the primary grid's memory writes are visible.
    asm volatile("griddepcontrol.wait;" ::: "memory");

    int lane = threadIdx.x;   // 32 threads; 64 partials -> one float2 per lane
    float2 p = *((const float2*)g_partials + lane);
    float v = p.x + p.y;
    v = warp_reduce(v);
    if (lane == 0) out[0] = v * (1.0f / (float)B_DIM);
}

extern "C" void kernel_launch(void* const* d_in, const int* in_sizes, int n_in,
                              void* d_out, int out_size) {
    const float* rule_prob  = (const float*)d_in[0];
    const float* token_prob = (const float*)d_in[1];
    const float* copy_prob  = (const float*)d_in[2];
    const int*   gt_rule    = (const int*)  d_in[3];
    const int*   gt_token   = (const int*)  d_in[4];
    const int*   gt_copy    = (const int*)  d_in[5];
    const float* mask       = (const float*)d_in[6];
    float* out = (float*)d_out;

    loss_gather_kernel<<<BLOCKS, THREADS>>>(rule_prob, token_prob, copy_prob,
                                            gt_rule, gt_token, gt_copy, mask);

    // Final reduction with Programmatic Dependent Launch: its launch latency
    // overlaps the gather kernel's execution.
    cudaLaunchAttribute attrs[1];
    attrs[0].id = cudaLaunchAttributeProgrammaticStreamSerialization;
    attrs[0].val.programmaticStreamSerializationAllowed = 1;

    cudaLaunchConfig_t cfg = {};
    cfg.gridDim  = dim3(1, 1, 1);
    cfg.blockDim = dim3(32, 1, 1);
    cfg.dynamicSmemBytes = 0;
    cfg.stream = 0;           // legacy default stream (the one the harness captures)
    cfg.attrs = attrs;
    cfg.numAttrs = 1;

    cudaError_t err = cudaLaunchKernelEx(&cfg, loss_final_kernel, out);
    if (err != cudaSuccess) {
        cudaGetLastError();
        // Fallback: plain serialized launch (still correct, no PDL overlap).
        loss_final_kernel<<<1, 32>>>(out);
    }
}